// round 11
// baseline (speedup 1.0000x reference)
#include <cuda_runtime.h>
#include <cuda_bf16.h>
#include <math.h>

// Problem constants
#define N_EMBED   512
#define EMBED_DIM 64
#define K_SPARSE  4
#define NSIG      16384           // 16 * 32 * 32
#define ZQ_ELEMS  1048576         // 16 * 64 * 32 * 32
#define N_BINS    33
#define WARPS_PER_BLOCK 8
#define OMP_BLOCKS (NSIG / WARPS_PER_BLOCK)   // 2048

typedef unsigned long long ull;

// Scratch (device globals: allocations are forbidden)
__device__ float g_DnT[N_EMBED * EMBED_DIM];     // normalized dict, atom-major [512][64]
__device__ float g_G  [N_EMBED * N_EMBED];       // Gram matrix [512][512]
__device__ float g_hbar[(size_t)NSIG * N_EMBED]; // correlations [16384][512] (32 MB)
__device__ float g_part[OMP_BLOCKS];             // per-block loss partials
__device__ int   g_ctr;                          // last-block counter (zero-init; reset by last block)

__device__ __forceinline__ unsigned redux_max_u32(unsigned v) {
    unsigned r;
    asm("redux.sync.max.u32 %0, %1, 0xffffffff;" : "=r"(r) : "r"(v));
    return r;
}
__device__ __forceinline__ unsigned redux_min_u32(unsigned v) {
    unsigned r;
    asm("redux.sync.min.u32 %0, %1, 0xffffffff;" : "=r"(r) : "r"(v));
    return r;
}
#define FMA2(acc, a, b) \
    asm("fma.rn.f32x2 %0, %1, %2, %0;" : "+l"(acc) : "l"(a), "l"(b))
__device__ __forceinline__ ull pack2(float v) {
    ull r; unsigned u = __float_as_uint(v);
    asm("mov.b64 %0, {%1, %1};" : "=l"(r) : "r"(u));
    return r;
}

// ---------------------------------------------------------------------------
// Kernel 1 (fused): blocks [0,1024) = h_bar tiles (normalize dict tile in-block,
// then f32x2 GEMM). Blocks [1024,1280) = Gram rows (2 per block), normalizing
// on the fly with the same dn = v*inv formula.
#define HBAR_BLOCKS 1024
__global__ void __launch_bounds__(256, 4) k_mid(const float* __restrict__ z_e,
                                                const float* __restrict__ dict) {
    __shared__ float Xs[EMBED_DIM][64];    // 16 KB (hbar)
    __shared__ float Ds[EMBED_DIM][128];   // 32 KB (hbar)
    __shared__ float pss[2][128];          // norm partials (hbar)
    __shared__ float invs[128];            // 1/norm per atom (hbar)
    __shared__ float di_n[2][EMBED_DIM];   // normalized row i (gram)
    __shared__ float sqv[2][EMBED_DIM];    // squares of column i (gram)
    __shared__ float invi[2];              // 1/norm of row i (gram)

    int blk = blockIdx.x;
    int tid = threadIdx.x;

    if (blk < HBAR_BLOCKS) {
        // ---- h_bar = Dn^T X. Tile: 64 signals x 128 atoms, K=64 ----
        int bsig  = (blk >> 2) << 6;
        int batom = (blk & 3) << 7;
        int b   = bsig >> 10;
        int hw0 = bsig & 1023;

        // X tile (float4, coalesced)
        {
            const float4* src = (const float4*)(z_e + b * 65536 + hw0);
            float4* dst = (float4*)&Xs[0][0];
            #pragma unroll
            for (int r = 0; r < 4; ++r) {
                int idx = tid + r * 256;
                int m = idx >> 4, j4 = idx & 15;
                dst[idx] = src[m * 256 + j4];
            }
        }
        // Raw dict tile + column sum-of-squares (two row-halves)
        int c  = tid & 127;
        int hh = tid >> 7;
        {
            float ss = 0.f;
            #pragma unroll 8
            for (int mi = 0; mi < 32; ++mi) {
                int m = hh * 32 + mi;
                float v = dict[m * N_EMBED + batom + c];
                Ds[m][c] = v;
                ss = fmaf(v, v, ss);
            }
            pss[hh][c] = ss;
        }
        __syncthreads();
        if (tid < 128)
            invs[tid] = 1.0f / fmaxf(sqrtf(pss[0][tid] + pss[1][tid]), 1e-10f);
        __syncthreads();
        // Rescale tile in smem (+ emit g_DnT from the 4 bsig==0 blocks)
        {
            float iv = invs[c];
            #pragma unroll 8
            for (int mi = 0; mi < 32; ++mi) {
                int m = hh * 32 + mi;
                float v = Ds[m][c] * iv;
                Ds[m][c] = v;
                if (blk < 4) g_DnT[(batom + c) * EMBED_DIM + m] = v;
            }
        }
        __syncthreads();

        int tx = tid & 15, ty = tid >> 4;
        ull acc[4][4];
        #pragma unroll
        for (int i = 0; i < 4; ++i)
            #pragma unroll
            for (int j = 0; j < 4; ++j) acc[i][j] = 0ull;

        #pragma unroll 4
        for (int m = 0; m < EMBED_DIM; ++m) {
            float4 xv = *(const float4*)&Xs[m][ty * 4];
            ull xx[4] = {pack2(xv.x), pack2(xv.y), pack2(xv.z), pack2(xv.w)};
            const ull* Dp = (const ull*)&Ds[m][0] + tx;
            ull dv[4];
            #pragma unroll
            for (int j = 0; j < 4; ++j) dv[j] = Dp[16 * j];
            #pragma unroll
            for (int i = 0; i < 4; ++i)
                #pragma unroll
                for (int j = 0; j < 4; ++j)
                    FMA2(acc[i][j], xx[i], dv[j]);
        }

        #pragma unroll
        for (int i = 0; i < 4; ++i) {
            int sig = bsig + ty * 4 + i;
            ull* row = (ull*)(g_hbar + (size_t)sig * N_EMBED + batom) + tx;
            #pragma unroll
            for (int j = 0; j < 4; ++j) row[16 * j] = acc[i][j];
        }
    } else {
        // ---- Gram rows: 2 rows per block ----
        int i0   = (blk - HBAR_BLOCKS) * 2;
        int half = tid >> 7;
        int col  = tid & 127;
        int i    = i0 + half;

        // Pass 1: sum-of-squares for this thread's 4 columns (split halves)
        float ssA[4] = {0.f, 0.f, 0.f, 0.f};
        float ssB[4] = {0.f, 0.f, 0.f, 0.f};
        #pragma unroll 4
        for (int m = 0; m < 32; ++m) {
            const float* row = dict + m * N_EMBED + col;
            #pragma unroll
            for (int t = 0; t < 4; ++t) {
                float v = row[t * 128];
                ssA[t] = fmaf(v, v, ssA[t]);
            }
        }
        #pragma unroll 4
        for (int m = 32; m < 64; ++m) {
            const float* row = dict + m * N_EMBED + col;
            #pragma unroll
            for (int t = 0; t < 4; ++t) {
                float v = row[t * 128];
                ssB[t] = fmaf(v, v, ssB[t]);
            }
        }
        float invj[4];
        #pragma unroll
        for (int t = 0; t < 4; ++t)
            invj[t] = 1.0f / fmaxf(sqrtf(ssA[t] + ssB[t]), 1e-10f);

        // Column i squares (64 threads per half)
        if (col < EMBED_DIM) sqv[half][col] = dict[col * N_EMBED + i];
        __syncthreads();
        if ((tid & 127) == 0) {
            float a = 0.f;
            #pragma unroll 8
            for (int m = 0; m < 32; ++m) { float v = sqv[half][m]; a = fmaf(v, v, a); }
            float bb = 0.f;
            #pragma unroll 8
            for (int m = 32; m < 64; ++m) { float v = sqv[half][m]; bb = fmaf(v, v, bb); }
            invi[half] = 1.0f / fmaxf(sqrtf(a + bb), 1e-10f);
        }
        __syncthreads();
        if (col < EMBED_DIM) di_n[half][col] = sqv[half][col] * invi[half];
        __syncthreads();

        // Pass 2: G[i,j] = sum_m dn_i[m] * (dict[m,j]*inv_j)
        float acc[4] = {0.f, 0.f, 0.f, 0.f};
        #pragma unroll 8
        for (int m = 0; m < EMBED_DIM; ++m) {
            float dm = di_n[half][m];
            const float* row = dict + m * N_EMBED + col;
            #pragma unroll
            for (int t = 0; t < 4; ++t)
                acc[t] = fmaf(dm, row[t * 128] * invj[t], acc[t]);
        }
        #pragma unroll
        for (int t = 0; t < 4; ++t)
            g_G[i * N_EMBED + col + t * 128] = acc[t];
    }
}

// ---------------------------------------------------------------------------
// Kernel 2: OMP, one warp per signal (lean 16 KB smem, 4 CTAs/SM).
__global__ void __launch_bounds__(256, 4) k_omp(const float* __restrict__ z_e,
                                                float* __restrict__ out) {
    __shared__ float sh_hbar[WARPS_PER_BLOCK][N_EMBED];      // 16 KB
    __shared__ float warp_loss[WARPS_PER_BLOCK];
    __shared__ int   sh_last;

    int wid  = threadIdx.x >> 5;
    int lane = threadIdx.x & 31;
    int s    = blockIdx.x * WARPS_PER_BLOCK + wid;
    int b    = s >> 10;
    int hw   = s & 1023;

    float* hb_row = sh_hbar[wid];

    float4 h[4];
    {
        const float4* hb4 = (const float4*)(g_hbar + (size_t)s * N_EMBED);
        float4* dst = (float4*)hb_row;
        #pragma unroll
        for (int q = 0; q < 4; ++q) {
            float4 v = hb4[q * 32 + lane];
            h[q] = v;
            dst[q * 32 + lane] = v;
        }
    }
    __syncwarp();
    float* hf = (float*)h;

    unsigned used = 0;
    int   sup[K_SPARSE];
    float hbs[K_SPARSE];
    float Lm[K_SPARSE][K_SPARSE];
    float coef[K_SPARSE];

    #pragma unroll
    for (int k = 0; k < K_SPARSE; ++k) {
        // argmax of |h| (used entries already zeroed in update)
        float mv[16];
        #pragma unroll
        for (int li = 0; li < 16; ++li) mv[li] = fabsf(hf[li]);
        float m0 = fmaxf(fmaxf(fmaxf(mv[0], mv[1]), fmaxf(mv[2], mv[3])),
                         fmaxf(fmaxf(mv[4], mv[5]), fmaxf(mv[6], mv[7])));
        float m1 = fmaxf(fmaxf(fmaxf(mv[8], mv[9]), fmaxf(mv[10], mv[11])),
                         fmaxf(fmaxf(mv[12], mv[13]), fmaxf(mv[14], mv[15])));
        unsigned M = redux_max_u32(__float_as_uint(fmaxf(m0, m1)));
        unsigned cand = 0xffffffffu;
        #pragma unroll
        for (int q = 0; q < 4; ++q)
            #pragma unroll
            for (int t = 0; t < 4; ++t) {
                int li = q * 4 + t;
                unsigned gi = q * 128 + lane * 4 + t;
                if (__float_as_uint(mv[li]) == M && gi < cand) cand = gi;
            }
        int bi = (int)redux_min_u32(cand);

        sup[k] = bi;
        hbs[k] = hb_row[bi];
        if (((bi >> 2) & 31) == lane)
            used |= 1u << ((((unsigned)bi >> 7) << 2) | (bi & 3));

        // incremental Cholesky (scalar G reads, L2-hot)
        if (k == 0) {
            Lm[0][0] = 1.f;
        } else {
            float w[3]; float ss = 0.f;
            #pragma unroll
            for (int a = 0; a < k; ++a) {
                float gv = g_G[sup[a] * N_EMBED + bi];
                #pragma unroll
                for (int c = 0; c < a; ++c) gv -= Lm[a][c] * w[c];
                w[a] = gv / Lm[a][a];
                ss += w[a] * w[a];
            }
            #pragma unroll
            for (int a = 0; a < k; ++a) Lm[k][a] = w[a];
            Lm[k][k] = sqrtf(fmaxf(1.f - ss, 1e-12f));
        }

        // solve L y = hbs ; L^T coef = y (size k+1)
        {
            float y[K_SPARSE];
            #pragma unroll
            for (int a = 0; a <= k; ++a) {
                float v = hbs[a];
                #pragma unroll
                for (int c = 0; c < a; ++c) v -= Lm[a][c] * y[c];
                y[a] = v / Lm[a][a];
            }
            #pragma unroll
            for (int a = k; a >= 0; --a) {
                float v = y[a];
                #pragma unroll
                for (int c = a + 1; c <= k; ++c) v -= Lm[c][a] * coef[c];
                coef[a] = v / Lm[a][a];
            }
        }

        // h = hbar - sum_{j<=k} coef[j]*G[sup[j],:], masked to 0 on used
        if (k < K_SPARSE - 1) {
            const float4* hb4 = (const float4*)hb_row;
            #pragma unroll
            for (int q = 0; q < 4; ++q) {
                float4 acc = hb4[q * 32 + lane];
                #pragma unroll
                for (int j = 0; j < K_SPARSE - 1; ++j) {
                    if (j <= k) {
                        float4 gv = ((const float4*)(g_G + sup[j] * N_EMBED))[q * 32 + lane];
                        acc.x -= coef[j] * gv.x;
                        acc.y -= coef[j] * gv.y;
                        acc.z -= coef[j] * gv.z;
                        acc.w -= coef[j] * gv.w;
                    }
                }
                float* af = (float*)&acc;
                #pragma unroll
                for (int t = 0; t < 4; ++t)
                    if ((used >> (q * 4 + t)) & 1u) af[t] = 0.f;
                h[q] = acc;
            }
        }
    }

    // quantize coefficients to 33 bins on [-2, 2]
    float cq[K_SPARSE];
    int   bq[K_SPARSE];
    #pragma unroll
    for (int j = 0; j < K_SPARSE; ++j) {
        float c  = fminf(fmaxf(coef[j], -2.f), 2.f);
        int   bi = (int)rintf((c + 2.f) * 8.f);
        bi = min(max(bi, 0), N_BINS - 1);
        bq[j] = bi;
        cq[j] = -2.f + 0.125f * (float)bi;
    }

    // tokens (exactly representable in fp32)
    if (lane == 0) {
        float* tok = out + ZQ_ELEMS + 1 + (size_t)s * K_SPARSE;
        #pragma unroll
        for (int j = 0; j < K_SPARSE; ++j)
            tok[j] = (float)(sup[j] * N_BINS + bq[j]);
    }

    // reconstruction, z_q_ste, loss (2 channels per lane)
    float lsum = 0.f;
    #pragma unroll
    for (int t = 0; t < 2; ++t) {
        int c = lane * 2 + t;
        float r = 0.f;
        #pragma unroll
        for (int j = 0; j < K_SPARSE; ++j)
            r = fmaf(cq[j], g_DnT[sup[j] * EMBED_DIM + c], r);
        int off = ((b * EMBED_DIM + c) << 10) + hw;
        float ze = z_e[off];
        float d  = r - ze;
        out[off] = ze + d;                 // z_q_ste
        lsum += d * d;
    }
    #pragma unroll
    for (int off = 16; off; off >>= 1) lsum += __shfl_xor_sync(0xffffffffu, lsum, off);
    if (lane == 0) warp_loss[wid] = lsum;
    __syncthreads();

    if (threadIdx.x == 0) {
        float t = 0.f;
        #pragma unroll
        for (int w = 0; w < WARPS_PER_BLOCK; ++w) t += warp_loss[w];
        g_part[blockIdx.x] = t;
        __threadfence();
        int old = atomicAdd(&g_ctr, 1);
        sh_last = (old == OMP_BLOCKS - 1) ? 1 : 0;
    }
    __syncthreads();

    if (sh_last) {
        float* red = sh_hbar[0];
        int t = threadIdx.x;
        float acc = 0.f;
        #pragma unroll
        for (int i = 0; i < OMP_BLOCKS / 256; ++i) acc += g_part[t + i * 256];
        red[t] = acc;
        __syncthreads();
        for (int o = 128; o > 0; o >>= 1) {
            if (t < o) red[t] += red[t + o];
            __syncthreads();
        }
        if (t == 0) {
            float mse = red[0] / (float)ZQ_ELEMS;
            out[ZQ_ELEMS] = mse + 0.25f * mse;   // dl_loss + COMMIT * e_loss
            g_ctr = 0;                            // reset for next replay
        }
    }
}

// ---------------------------------------------------------------------------
extern "C" void kernel_launch(void* const* d_in, const int* in_sizes, int n_in,
                              void* d_out, int out_size) {
    const float* z_e  = (const float*)d_in[0];
    const float* dict = (const float*)d_in[1];
    float* out = (float*)d_out;

    k_mid<<<HBAR_BLOCKS + N_EMBED / 2, 256>>>(z_e, dict);
    k_omp<<<OMP_BLOCKS, 256>>>(z_e, out);
}

// round 13
// speedup vs baseline: 1.1571x; 1.1571x over previous
#include <cuda_runtime.h>
#include <cuda_bf16.h>
#include <math.h>

// Problem constants
#define N_EMBED   512
#define EMBED_DIM 64
#define K_SPARSE  4
#define NSIG      16384           // 16 * 32 * 32
#define ZQ_ELEMS  1048576         // 16 * 64 * 32 * 32
#define N_BINS    33
#define WARPS_PER_BLOCK 8
#define OMP_BLOCKS (NSIG / WARPS_PER_BLOCK)   // 2048

typedef unsigned long long ull;

// Scratch (device globals: allocations are forbidden)
__device__ float g_Dn [EMBED_DIM * N_EMBED];     // normalized dict, dim-major [64][512]
__device__ float g_DnT[N_EMBED * EMBED_DIM];     // normalized dict, atom-major [512][64]
__device__ float g_G  [N_EMBED * N_EMBED];       // Gram matrix [512][512]
__device__ float g_hbar[(size_t)NSIG * N_EMBED]; // correlations [16384][512] (32 MB)
__device__ float g_part[OMP_BLOCKS];             // per-block loss partials
__device__ int   g_ctr;                          // last-block counter

__device__ __forceinline__ unsigned redux_max_u32(unsigned v) {
    unsigned r;
    asm("redux.sync.max.u32 %0, %1, 0xffffffff;" : "=r"(r) : "r"(v));
    return r;
}
__device__ __forceinline__ unsigned redux_min_u32(unsigned v) {
    unsigned r;
    asm("redux.sync.min.u32 %0, %1, 0xffffffff;" : "=r"(r) : "r"(v));
    return r;
}
#define FMA2(acc, a, b) \
    asm("fma.rn.f32x2 %0, %1, %2, %0;" : "+l"(acc) : "l"(a), "l"(b))
__device__ __forceinline__ ull pack2(float v) {
    ull r; unsigned u = __float_as_uint(v);
    asm("mov.b64 %0, {%1, %1};" : "=l"(r) : "r"(u));
    return r;
}

// ---------------------------------------------------------------------------
// Kernel 1: normalize dictionary columns (R7 version; 5.3 us measured).
__global__ void k_norm(const float* __restrict__ dict) {
    if (blockIdx.x == 0 && threadIdx.x == 0) g_ctr = 0;
    int n = blockIdx.x;
    int m = threadIdx.x;
    float v = dict[m * N_EMBED + n];
    __shared__ float sh[EMBED_DIM];
    sh[m] = v * v;
    __syncthreads();
    for (int o = 32; o > 0; o >>= 1) {
        if (m < o) sh[m] += sh[m + o];
        __syncthreads();
    }
    float nr = fmaxf(sqrtf(sh[0]), 1e-10f);
    float dn = v / nr;
    g_Dn [m * N_EMBED + n]   = dn;
    g_DnT[n * EMBED_DIM + m] = dn;
}

// ---------------------------------------------------------------------------
// Kernel 2 (merged): blocks [0,1024) compute h_bar tiles (f32x2 GEMM),
// blocks [1024,1280) compute Gram rows (2 rows per block).
#define HBAR_BLOCKS 1024
__global__ void __launch_bounds__(256, 4) k_mid(const float* __restrict__ z_e) {
    int blk = blockIdx.x;
    int tid = threadIdx.x;

    if (blk < HBAR_BLOCKS) {
        // ---- h_bar = Dn^T X. Tile: 64 signals x 128 atoms, K=64 ----
        __shared__ float Xs[EMBED_DIM][64];    // 16 KB
        __shared__ float Ds[EMBED_DIM][128];   // 32 KB

        int bsig  = (blk >> 2) << 6;
        int batom = (blk & 3) << 7;
        int b   = bsig >> 10;
        int hw0 = bsig & 1023;

        {
            const float4* src = (const float4*)(z_e + b * 65536 + hw0);
            float4* dst = (float4*)&Xs[0][0];
            #pragma unroll
            for (int r = 0; r < 4; ++r) {
                int idx = tid + r * 256;
                int m = idx >> 4, j4 = idx & 15;
                dst[idx] = src[m * 256 + j4];
            }
        }
        {
            const float4* src = (const float4*)(g_Dn + batom);
            float4* dst = (float4*)&Ds[0][0];
            #pragma unroll
            for (int r = 0; r < 8; ++r) {
                int idx = tid + r * 256;
                int m = idx >> 5, a4 = idx & 31;
                dst[idx] = src[m * 128 + a4];
            }
        }
        __syncthreads();

        int tx = tid & 15, ty = tid >> 4;
        ull acc[4][4];
        #pragma unroll
        for (int i = 0; i < 4; ++i)
            #pragma unroll
            for (int j = 0; j < 4; ++j) acc[i][j] = 0ull;

        #pragma unroll 4
        for (int m = 0; m < EMBED_DIM; ++m) {
            float4 xv = *(const float4*)&Xs[m][ty * 4];
            ull xx[4] = {pack2(xv.x), pack2(xv.y), pack2(xv.z), pack2(xv.w)};
            const ull* Dp = (const ull*)&Ds[m][0] + tx;
            ull dv[4];
            #pragma unroll
            for (int j = 0; j < 4; ++j) dv[j] = Dp[16 * j];
            #pragma unroll
            for (int i = 0; i < 4; ++i)
                #pragma unroll
                for (int j = 0; j < 4; ++j)
                    FMA2(acc[i][j], xx[i], dv[j]);
        }

        #pragma unroll
        for (int i = 0; i < 4; ++i) {
            int sig = bsig + ty * 4 + i;
            ull* row = (ull*)(g_hbar + (size_t)sig * N_EMBED + batom) + tx;
            #pragma unroll
            for (int j = 0; j < 4; ++j) row[16 * j] = acc[i][j];
        }
    } else {
        // ---- Gram rows: 2 rows per block, 128 threads per row ----
        __shared__ float di[2][EMBED_DIM];
        int i0 = (blk - HBAR_BLOCKS) * 2;
        if (tid < 2 * EMBED_DIM)
            di[tid >> 6][tid & 63] = g_DnT[(i0 + (tid >> 6)) * EMBED_DIM + (tid & 63)];
        __syncthreads();
        int half = tid >> 7;
        int col  = tid & 127;
        int i = i0 + half;
        float acc[4] = {0.f, 0.f, 0.f, 0.f};
        #pragma unroll 8
        for (int m = 0; m < EMBED_DIM; ++m) {
            float dm = di[half][m];
            const float* row = g_Dn + m * N_EMBED + col;
            #pragma unroll
            for (int t = 0; t < 4; ++t)
                acc[t] = fmaf(dm, row[t * 128], acc[t]);
        }
        #pragma unroll
        for (int t = 0; t < 4; ++t)
            g_G[i * N_EMBED + col + t * 128] = acc[t];
    }
}

// ---------------------------------------------------------------------------
// Kernel 3: OMP, one warp per signal (R6 core — measured fastest).
// New: coalesced block-cooperative epilogue + fused loss reduction.
__global__ void __launch_bounds__(256, 3) k_omp(const float* __restrict__ z_e,
                                                float* __restrict__ out) {
    __shared__ float sh_hbar[WARPS_PER_BLOCK][N_EMBED];      // 16 KB
    __shared__ int   sh_sup[WARPS_PER_BLOCK][K_SPARSE];
    __shared__ float sh_cq [WARPS_PER_BLOCK][K_SPARSE];
    __shared__ float warp_loss[WARPS_PER_BLOCK];
    __shared__ int   sh_last;

    int wid  = threadIdx.x >> 5;
    int lane = threadIdx.x & 31;
    int s    = blockIdx.x * WARPS_PER_BLOCK + wid;

    float* hb_row = sh_hbar[wid];

    // Load correlations -> h regs + full shared hbar copy
    float4 h[4];
    {
        const float4* hb4 = (const float4*)(g_hbar + (size_t)s * N_EMBED);
        float4* dst = (float4*)hb_row;
        #pragma unroll
        for (int q = 0; q < 4; ++q) {
            float4 v = hb4[q * 32 + lane];
            h[q] = v;
            dst[q * 32 + lane] = v;
        }
    }
    __syncwarp();
    float* hf = (float*)h;

    unsigned used = 0;
    int   sup[K_SPARSE];
    float hbs[K_SPARSE];
    float Lm[K_SPARSE][K_SPARSE];
    float coef[K_SPARSE];

    #pragma unroll
    for (int k = 0; k < K_SPARSE; ++k) {
        // masked argmax of |h| (masked -> 0, first-max-index wins)  [R6 core]
        float best = -1.f; int bidx = 0;
        #pragma unroll
        for (int q = 0; q < 4; ++q) {
            #pragma unroll
            for (int t = 0; t < 4; ++t) {
                int li = q * 4 + t;                      // ascending gi order
                float mv = ((used >> li) & 1u) ? 0.0f : fabsf(hf[li]);
                int gi = q * 128 + lane * 4 + t;
                if (mv > best) { best = mv; bidx = gi; }
            }
        }
        unsigned M = redux_max_u32(__float_as_uint(best));
        unsigned cand = (__float_as_uint(best) == M) ? (unsigned)bidx : 0xffffffffu;
        int bi = (int)redux_min_u32(cand);

        sup[k] = bi;
        hbs[k] = hb_row[bi];                       // broadcast LDS
        if (((bi >> 2) & 31) == lane)
            used |= 1u << ((((unsigned)bi >> 7) << 2) | (bi & 3));

        // incremental Cholesky (scalar G reads, L2-hot)
        if (k == 0) {
            Lm[0][0] = 1.f;
        } else {
            float w[3]; float ss = 0.f;
            #pragma unroll
            for (int a = 0; a < k; ++a) {
                float gv = g_G[sup[a] * N_EMBED + bi];
                #pragma unroll
                for (int c = 0; c < a; ++c) gv -= Lm[a][c] * w[c];
                w[a] = gv / Lm[a][a];
                ss += w[a] * w[a];
            }
            #pragma unroll
            for (int a = 0; a < k; ++a) Lm[k][a] = w[a];
            Lm[k][k] = sqrtf(fmaxf(1.f - ss, 1e-12f));
        }

        // solve L y = hbs ; L^T coef = y (size k+1)
        {
            float y[K_SPARSE];
            #pragma unroll
            for (int a = 0; a <= k; ++a) {
                float v = hbs[a];
                #pragma unroll
                for (int c = 0; c < a; ++c) v -= Lm[a][c] * y[c];
                y[a] = v / Lm[a][a];
            }
            #pragma unroll
            for (int a = k; a >= 0; --a) {
                float v = y[a];
                #pragma unroll
                for (int c = a + 1; c <= k; ++c) v -= Lm[c][a] * coef[c];
                coef[a] = v / Lm[a][a];
            }
        }

        // h = hbar - sum_{j<=k} coef[j]*G[sup[j],:]  [R6 core]
        if (k < K_SPARSE - 1) {
            const float4* hb4 = (const float4*)hb_row;
            #pragma unroll
            for (int q = 0; q < 4; ++q) {
                float4 acc = hb4[q * 32 + lane];
                #pragma unroll
                for (int j = 0; j < K_SPARSE - 1; ++j) {
                    if (j <= k) {
                        float4 gv = ((const float4*)(g_G + sup[j] * N_EMBED))[q * 32 + lane];
                        acc.x -= coef[j] * gv.x;
                        acc.y -= coef[j] * gv.y;
                        acc.z -= coef[j] * gv.z;
                        acc.w -= coef[j] * gv.w;
                    }
                }
                h[q] = acc;
            }
        }
    }

    // quantize coefficients to 33 bins on [-2, 2]
    float cq[K_SPARSE];
    int   bq[K_SPARSE];
    #pragma unroll
    for (int j = 0; j < K_SPARSE; ++j) {
        float c  = fminf(fmaxf(coef[j], -2.f), 2.f);
        int   bi = (int)rintf((c + 2.f) * 8.f);
        bi = min(max(bi, 0), N_BINS - 1);
        bq[j] = bi;
        cq[j] = -2.f + 0.125f * (float)bi;
    }

    // tokens + stash support/coeffs for the cooperative epilogue
    if (lane == 0) {
        float* tok = out + ZQ_ELEMS + 1 + (size_t)s * K_SPARSE;
        #pragma unroll
        for (int j = 0; j < K_SPARSE; ++j) {
            tok[j] = (float)(sup[j] * N_BINS + bq[j]);
            sh_sup[wid][j] = sup[j];
            sh_cq [wid][j] = cq[j];
        }
    }
    __syncthreads();

    // ---- coalesced epilogue: 8 consecutive-hw signals, channel-major ----
    // element idx e in [0,512): c = e>>3, sl = e&7; thread handles e=tid, tid+256.
    int s0  = blockIdx.x * WARPS_PER_BLOCK;          // first signal of block
    int b0  = s0 >> 10;
    int hw0 = s0 & 1023;
    float lsum = 0.f;
    #pragma unroll
    for (int r = 0; r < 2; ++r) {
        int e  = threadIdx.x + r * 256;
        int c  = e >> 3;
        int sl = e & 7;
        float rec = 0.f;
        #pragma unroll
        for (int j = 0; j < K_SPARSE; ++j)
            rec = fmaf(sh_cq[sl][j], g_DnT[sh_sup[sl][j] * EMBED_DIM + c], rec);
        int off = ((b0 * EMBED_DIM + c) << 10) + hw0 + sl;
        float ze = z_e[off];
        float d  = rec - ze;
        out[off] = ze + d;                 // z_q_ste
        lsum += d * d;
    }
    #pragma unroll
    for (int off = 16; off; off >>= 1) lsum += __shfl_xor_sync(0xffffffffu, lsum, off);
    if (lane == 0) warp_loss[wid] = lsum;
    __syncthreads();

    // per-block partial + last-block detection
    if (threadIdx.x == 0) {
        float t = 0.f;
        #pragma unroll
        for (int w = 0; w < WARPS_PER_BLOCK; ++w) t += warp_loss[w];
        g_part[blockIdx.x] = t;
        __threadfence();
        int old = atomicAdd(&g_ctr, 1);
        sh_last = (old == OMP_BLOCKS - 1) ? 1 : 0;
    }
    __syncthreads();

    // last block: deterministic fixed-order final reduction
    if (sh_last) {
        float* red = sh_hbar[0];
        int t = threadIdx.x;
        float acc = 0.f;
        #pragma unroll
        for (int i = 0; i < OMP_BLOCKS / 256; ++i) acc += g_part[t + i * 256];
        red[t] = acc;
        __syncthreads();
        for (int o = 128; o > 0; o >>= 1) {
            if (t < o) red[t] += red[t + o];
            __syncthreads();
        }
        if (t == 0) {
            float mse = red[0] / (float)ZQ_ELEMS;
            out[ZQ_ELEMS] = mse + 0.25f * mse;   // dl_loss + COMMIT * e_loss
        }
    }
}

// ---------------------------------------------------------------------------
extern "C" void kernel_launch(void* const* d_in, const int* in_sizes, int n_in,
                              void* d_out, int out_size) {
    const float* z_e  = (const float*)d_in[0];
    const float* dict = (const float*)d_in[1];
    float* out = (float*)d_out;

    k_norm<<<N_EMBED, EMBED_DIM>>>(dict);
    k_mid<<<HBAR_BLOCKS + N_EMBED / 2, 256>>>(z_e);
    k_omp<<<OMP_BLOCKS, 256>>>(z_e, out);
}